// round 15
// baseline (speedup 1.0000x reference)
#include <cuda_runtime.h>
#include <cuda_fp16.h>
#include <math.h>
#include <stdint.h>

// ---------------------------------------------------------------------------
// Problem constants (B = 1)
// ---------------------------------------------------------------------------
#define LTOK 4096
#define DMODEL 3072
#define NHEAD 24
#define HDIM 128
#define MLPD 12288
#define N1 (3 * DMODEL + MLPD)   // 21504
#define K2 (DMODEL + MLPD)       // 15360
#define QKVW (3 * DMODEL)        // 9216
#define EPSV 1e-6f
#define SM_SCALE 0.08838834764831843f
#define LOG2E 1.4426950408889634f

// ---------------------------------------------------------------------------
// Scratch
// ---------------------------------------------------------------------------
__device__ float  g_sv[DMODEL];
__device__ float  g_m[3 * DMODEL];
__device__ __half g_xmodh[(size_t)LTOK * DMODEL];
__device__ __half g_qh[(size_t)NHEAD * LTOK * HDIM];   // pre-scaled by SM_SCALE*log2e
__device__ __half g_kh[(size_t)NHEAD * LTOK * HDIM];
__device__ __half g_vh[(size_t)NHEAD * LTOK * HDIM];
__device__ __half g_cath[(size_t)LTOK * K2];           // [attn | gelu(mlp)]
__device__ __half g_w1h[(size_t)N1 * DMODEL];
__device__ __half g_w2h[(size_t)DMODEL * K2];
__device__ float  g_out1[(size_t)LTOK * DMODEL];       // GEMM2a partial (mlp@W2b + b2)

// ---------------------------------------------------------------------------
// helpers
// ---------------------------------------------------------------------------
__device__ __forceinline__ uint32_t smem_u32(const void* p) {
    uint32_t a;
    asm("{ .reg .u64 t; cvta.to.shared.u64 t, %1; cvt.u32.u64 %0, t; }"
        : "=r"(a) : "l"(p));
    return a;
}
__device__ __forceinline__ void cp_async16(uint32_t s, const void* g) {
    asm volatile("cp.async.cg.shared.global [%0], [%1], 16;" :: "r"(s), "l"(g) : "memory");
}
__device__ __forceinline__ void mma_f16(float* c, const uint32_t* a,
                                        uint32_t b0, uint32_t b1) {
    asm volatile(
        "mma.sync.aligned.m16n8k16.row.col.f32.f16.f16.f32 "
        "{%0,%1,%2,%3}, {%4,%5,%6,%7}, {%8,%9}, {%0,%1,%2,%3};"
        : "+f"(c[0]), "+f"(c[1]), "+f"(c[2]), "+f"(c[3])
        : "r"(a[0]), "r"(a[1]), "r"(a[2]), "r"(a[3]), "r"(b0), "r"(b1));
}
__device__ __forceinline__ void ldsm4(uint32_t* r, uint32_t addr) {
    asm volatile("ldmatrix.sync.aligned.m8n8.x4.shared.b16 {%0,%1,%2,%3}, [%4];"
                 : "=r"(r[0]), "=r"(r[1]), "=r"(r[2]), "=r"(r[3]) : "r"(addr));
}
__device__ __forceinline__ void ldsm4t(uint32_t* r, uint32_t addr) {
    asm volatile("ldmatrix.sync.aligned.m8n8.x4.trans.shared.b16 {%0,%1,%2,%3}, [%4];"
                 : "=r"(r[0]), "=r"(r[1]), "=r"(r[2]), "=r"(r[3]) : "r"(addr));
}
__device__ __forceinline__ uint32_t packh2(float lo, float hi) {
    __half2 h = __floats2half2_rn(lo, hi);
    return *reinterpret_cast<uint32_t*>(&h);
}
__device__ __forceinline__ float gelu_t(float x) {
    return 0.5f * x * (1.0f + tanhf(0.7978845608028654f * (x + 0.044715f * x * x * x)));
}

// ---------------------------------------------------------------------------
// small kernels
// ---------------------------------------------------------------------------
__global__ void silu_k(const float* __restrict__ vec) {
    int i = blockIdx.x * blockDim.x + threadIdx.x;
    if (i < DMODEL) {
        float v = vec[i];
        g_sv[i] = v / (1.0f + expf(-v));
    }
}

__global__ void mod_gemv(const float* __restrict__ mw, const float* __restrict__ mb) {
    int j = blockIdx.x * 8 + (threadIdx.x >> 5);
    int lane = threadIdx.x & 31;
    const float* wr = mw + (size_t)j * DMODEL;
    float s = 0.f;
    for (int k = lane; k < DMODEL; k += 32) s += g_sv[k] * wr[k];
#pragma unroll
    for (int o = 16; o; o >>= 1) s += __shfl_down_sync(0xffffffffu, s, o);
    if (lane == 0) g_m[j] = s + mb[j];
}

__device__ __forceinline__ float block_sum256(float v, float* buf) {
#pragma unroll
    for (int o = 16; o; o >>= 1) v += __shfl_down_sync(0xffffffffu, v, o);
    int w = threadIdx.x >> 5;
    if ((threadIdx.x & 31) == 0) buf[w] = v;
    __syncthreads();
    float s = 0.f;
#pragma unroll
    for (int i = 0; i < 8; i++) s += buf[i];
    return s;
}

__global__ void __launch_bounds__(256) ln_mod(const float* __restrict__ x) {
    __shared__ float xs[DMODEL];
    __shared__ float rbuf[8];
    int row = blockIdx.x;
    const float* xr = x + (size_t)row * DMODEL;
    float s = 0.f;
    for (int i = threadIdx.x; i < DMODEL; i += 256) {
        float v = xr[i];
        xs[i] = v;
        s += v;
    }
    float mu = block_sum256(s, rbuf) * (1.0f / DMODEL);
    __syncthreads();
    float s2 = 0.f;
    for (int i = threadIdx.x; i < DMODEL; i += 256) {
        float d = xs[i] - mu;
        s2 += d * d;
    }
    float var = block_sum256(s2, rbuf) * (1.0f / DMODEL);
    float rstd = rsqrtf(var + EPSV);
    __half* xm = g_xmodh + (size_t)row * DMODEL;
    for (int i = threadIdx.x; i < DMODEL; i += 256) {
        float n = (xs[i] - mu) * rstd;
        xm[i] = __float2half_rn((1.0f + g_m[DMODEL + i]) * n + g_m[i]);
    }
}

// fp32 -> fp16 weight conversion
#define W1_N4 ((N1 * DMODEL) / 4)
#define W2_N4 ((DMODEL * K2) / 4)
__global__ void __launch_bounds__(256) cvt_h_k(const float* __restrict__ src,
                                               __half* __restrict__ dst, int n4) {
    int i = blockIdx.x * 256 + threadIdx.x;
    if (i < n4) {
        float4 v = ((const float4*)src)[i];
        uint2 u = make_uint2(packh2(v.x, v.y), packh2(v.z, v.w));
        *(uint2*)(dst + (size_t)i * 4) = u;
    }
}

// ---------------------------------------------------------------------------
// fp16 mma.sync GEMM (NT): CTA tile 128x128, 4 warps (2x2), warp tile 64x64.
// 2 CTAs/SM. BK=32, 3-stage cp.async, ldmatrix, 1 sync/chunk. lda/ldb allow
// sub-K GEMMs; bn0 offsets the column-block base for sub-N launches.
// EPI==0: GEMM1 fused epilogue (q/k rmsnorm+rope, v relayout, mlp gelu)
// EPI==2: GEMM2a -> C = acc + bias            (fp32 partial)
// EPI==3: GEMM2b -> C = xres + gate * (partial + acc)
// ---------------------------------------------------------------------------
#define BM 128
#define BN 128
#define BK 32
#define NSTG 3
#define AROWH 40
#define TILEH (BM * AROWH)
#define TILEB (TILEH * 2)                 // 10240 B
#define GEMM_SMEM (NSTG * 2 * TILEB)      // 61440 B
#define GTHREADS 128

__device__ __forceinline__ void ld_stage(uint32_t As, uint32_t Bs,
                                         const __half* __restrict__ Ag,
                                         const __half* __restrict__ Bg,
                                         int lda, int ldb, int kb, int tid) {
#pragma unroll
    for (int it = 0; it < 4; ++it) {
        int id = it * GTHREADS + tid;
        int row = id >> 2, c = id & 3;
        uint32_t off = (uint32_t)(row * AROWH * 2 + c * 16);
        cp_async16(As + off, Ag + (size_t)row * lda + kb + c * 8);
        cp_async16(Bs + off, Bg + (size_t)row * ldb + kb + c * 8);
    }
}

template <int EPI>
__global__ void __launch_bounds__(GTHREADS, 2)
mm_gemm(const __half* __restrict__ A, const __half* __restrict__ B,
        float* __restrict__ C, int Nt, int K, int lda, int ldb, int bn0,
        const float* __restrict__ bias,
        const float* __restrict__ xres, const float* __restrict__ gate,
        const float* __restrict__ partial,
        const float* __restrict__ pe,
        const float* __restrict__ q_scale, const float* __restrict__ k_scale) {
    extern __shared__ __half smh[];
    const uint32_t sA = smem_u32(smh);
    const uint32_t sB = sA + NSTG * TILEB;

    const int tid = threadIdx.x;
    const int wid = tid >> 5, lane = tid & 31;
    const int gp = lane >> 2, qd = lane & 3;
    const int warpM = (wid >> 1) * 64;
    const int warpN = (wid & 1) * 64;
    const int bm = blockIdx.x * BM;
    const int bn = blockIdx.y * BN + bn0;

    const __half* Ag = A + (size_t)bm * lda;
    const __half* Bg = B + (size_t)bn * ldb;
    const int nch = K / BK;

    float acc[4][8][4] = {};

#pragma unroll
    for (int p = 0; p < NSTG - 1; ++p) {
        ld_stage(sA + p * TILEB, sB + p * TILEB, Ag, Bg, lda, ldb, p * BK, tid);
        asm volatile("cp.async.commit_group;" ::: "memory");
    }

    const uint32_t aOff = (uint32_t)((warpM + (lane & 15)) * AROWH + (lane >> 4) * 8) * 2;
    const uint32_t bOff = (uint32_t)((warpN + (lane & 7)) * AROWH + (lane >> 3) * 8) * 2;

    for (int j = 0; j < nch; ++j) {
        asm volatile("cp.async.wait_group %0;" :: "n"(NSTG - 2) : "memory");
        __syncthreads();
        const int c = j + NSTG - 1;
        if (c < nch) {
            const int st = c % NSTG;
            ld_stage(sA + st * TILEB, sB + st * TILEB, Ag, Bg, lda, ldb, c * BK, tid);
        }
        asm volatile("cp.async.commit_group;" ::: "memory");

        const uint32_t asb = sA + (j % NSTG) * TILEB + aOff;
        const uint32_t bsb = sB + (j % NSTG) * TILEB + bOff;

        uint32_t bf[8][4];
#pragma unroll
        for (int nt = 0; nt < 8; ++nt)
            ldsm4(bf[nt], bsb + (uint32_t)(nt * 8 * AROWH) * 2);

#pragma unroll
        for (int ks = 0; ks < 2; ++ks) {
            uint32_t af[4][4];
#pragma unroll
            for (int mt = 0; mt < 4; ++mt)
                ldsm4(af[mt], asb + (uint32_t)(mt * 16 * AROWH + ks * 16) * 2);
#pragma unroll
            for (int mt = 0; mt < 4; ++mt)
#pragma unroll
                for (int nt = 0; nt < 8; ++nt)
                    mma_f16(acc[mt][nt], af[mt], bf[nt][2 * ks], bf[nt][2 * ks + 1]);
        }
    }

    // epilogue
    if (EPI == 0) {
        const int btype = bn / DMODEL;     // 0=q, 1=k, 2=v, >=3 mlp
        if (btype >= 3) {
#pragma unroll
            for (int nt = 0; nt < 8; ++nt) {
                const int col = bn + warpN + nt * 8 + 2 * qd;
                const float b0 = bias[col], b1v = bias[col + 1];
#pragma unroll
                for (int mt = 0; mt < 4; ++mt) {
#pragma unroll
                    for (int h2 = 0; h2 < 2; ++h2) {
                        const int row = bm + warpM + mt * 16 + gp + h2 * 8;
                        float v0 = acc[mt][nt][h2 * 2 + 0] + b0;
                        float v1 = acc[mt][nt][h2 * 2 + 1] + b1v;
                        *(uint32_t*)(g_cath + (size_t)row * K2 + (col - 2 * DMODEL)) =
                            packh2(gelu_t(v0), gelu_t(v1));
                    }
                }
            }
        } else {
            const int hh = (bn % DMODEL) >> 7;
            float ssp[4][2] = {};
#pragma unroll
            for (int nt = 0; nt < 8; ++nt) {
                const int col = bn + warpN + nt * 8 + 2 * qd;
                const float b0 = bias[col], b1v = bias[col + 1];
#pragma unroll
                for (int mt = 0; mt < 4; ++mt)
#pragma unroll
                    for (int h2 = 0; h2 < 2; ++h2) {
                        float v0 = acc[mt][nt][h2 * 2 + 0] + b0;
                        float v1 = acc[mt][nt][h2 * 2 + 1] + b1v;
                        acc[mt][nt][h2 * 2 + 0] = v0;
                        acc[mt][nt][h2 * 2 + 1] = v1;
                        if (btype < 2) ssp[mt][h2] += v0 * v0 + v1 * v1;
                    }
            }
            if (btype == 2) {
#pragma unroll
                for (int mt = 0; mt < 4; ++mt)
#pragma unroll
                    for (int h2 = 0; h2 < 2; ++h2) {
                        const int grow = bm + warpM + mt * 16 + gp + h2 * 8;
#pragma unroll
                        for (int nt = 0; nt < 8; ++nt) {
                            const int c0 = warpN + nt * 8 + 2 * qd;
                            *(uint32_t*)(g_vh + ((size_t)hh * LTOK + grow) * HDIM + c0) =
                                packh2(acc[mt][nt][h2 * 2 + 0], acc[mt][nt][h2 * 2 + 1]);
                        }
                    }
            } else {
#pragma unroll
                for (int mt = 0; mt < 4; ++mt)
#pragma unroll
                    for (int h2 = 0; h2 < 2; ++h2) {
                        ssp[mt][h2] += __shfl_xor_sync(0xffffffffu, ssp[mt][h2], 1);
                        ssp[mt][h2] += __shfl_xor_sync(0xffffffffu, ssp[mt][h2], 2);
                    }
                float* red = (float*)smh;
                __syncthreads();
                if (qd == 0) {
#pragma unroll
                    for (int mt = 0; mt < 4; ++mt)
#pragma unroll
                        for (int h2 = 0; h2 < 2; ++h2)
                            red[(warpM + mt * 16 + gp + h2 * 8) * 2 + (warpN >> 6)] =
                                ssp[mt][h2];
                }
                __syncthreads();
                const float* sc = (btype == 0) ? q_scale : k_scale;
                __half* dst = (btype == 0) ? g_qh : g_kh;
                const float fin = (btype == 0) ? SM_SCALE * LOG2E : 1.0f;
#pragma unroll
                for (int mt = 0; mt < 4; ++mt)
#pragma unroll
                    for (int h2 = 0; h2 < 2; ++h2) {
                        const int lrow = warpM + mt * 16 + gp + h2 * 8;
                        const float ss = red[lrow * 2 + 0] + red[lrow * 2 + 1];
                        const float rstd = rsqrtf(ss * (1.0f / HDIM) + EPSV);
                        const int grow = bm + lrow;
#pragma unroll
                        for (int nt = 0; nt < 8; ++nt) {
                            const int c0 = warpN + nt * 8 + 2 * qd;
                            float v0 = acc[mt][nt][h2 * 2 + 0] * rstd * sc[c0];
                            float v1 = acc[mt][nt][h2 * 2 + 1] * rstd * sc[c0 + 1];
                            float4 f = *(const float4*)(pe +
                                ((size_t)grow * (HDIM / 2) + (c0 >> 1)) * 4);
                            float o0 = f.x * v0 + f.y * v1;
                            float o1 = f.z * v0 + f.w * v1;
                            *(uint32_t*)(dst + ((size_t)hh * LTOK + grow) * HDIM + c0) =
                                packh2(o0 * fin, o1 * fin);
                        }
                    }
            }
        }
    } else if (EPI == 2) {
#pragma unroll
        for (int nt = 0; nt < 8; ++nt) {
            const int col = bn + warpN + nt * 8 + 2 * qd;
            const float b0 = bias[col], b1v = bias[col + 1];
#pragma unroll
            for (int mt = 0; mt < 4; ++mt) {
#pragma unroll
                for (int h2 = 0; h2 < 2; ++h2) {
                    const int row = bm + warpM + mt * 16 + gp + h2 * 8;
                    const size_t off = (size_t)row * Nt + col;
                    *(float2*)(C + off) = make_float2(acc[mt][nt][h2 * 2 + 0] + b0,
                                                      acc[mt][nt][h2 * 2 + 1] + b1v);
                }
            }
        }
    } else {
#pragma unroll
        for (int nt = 0; nt < 8; ++nt) {
            const int col = bn + warpN + nt * 8 + 2 * qd;
            const float g0 = gate[col], g1 = gate[col + 1];
#pragma unroll
            for (int mt = 0; mt < 4; ++mt) {
#pragma unroll
                for (int h2 = 0; h2 < 2; ++h2) {
                    const int row = bm + warpM + mt * 16 + gp + h2 * 8;
                    const size_t off = (size_t)row * Nt + col;
                    float2 xr = *(const float2*)(xres + off);
                    float2 pp = *(const float2*)(partial + off);
                    float v0 = xr.x + g0 * (pp.x + acc[mt][nt][h2 * 2 + 0]);
                    float v1 = xr.y + g1 * (pp.y + acc[mt][nt][h2 * 2 + 1]);
                    *(float2*)(C + off) = make_float2(v0, v1);
                }
            }
        }
    }
}

// ---------------------------------------------------------------------------
// Flash attention fp16 mma: Q tile 64, 128 threads, 2 CTAs/SM (R13 validated)
// ---------------------------------------------------------------------------
#define KSH 136
#define KVBUF (64 * KSH * 2)
#define FL_SMEM (4 * KVBUF)
#define FTHREADS 128

__device__ __forceinline__ void load_kv(uint32_t kd, uint32_t vd,
                                        const __half* __restrict__ Kg,
                                        const __half* __restrict__ Vg,
                                        int kt, int tid) {
#pragma unroll
    for (int it = 0; it < 8; ++it) {
        int id = it * FTHREADS + tid;
        int row = id >> 4, c = id & 15;
        uint32_t off = (uint32_t)(row * KSH * 2 + c * 16);
        const size_t goff = (size_t)(kt + row) * HDIM + c * 8;
        cp_async16(kd + off, Kg + goff);
        cp_async16(vd + off, Vg + goff);
    }
}

__global__ void __launch_bounds__(FTHREADS, 2) flash_h() {
    extern __shared__ __half smh[];
    const uint32_t kbase0 = smem_u32(smh);
    const uint32_t vbase0 = kbase0 + 2 * KVBUF;

    const int h = blockIdx.y;
    const int qb = blockIdx.x * 64;
    const int tid = threadIdx.x;
    const int w = tid >> 5, lane = tid & 31;
    const int gp = lane >> 2, qd = lane & 3;

    const __half* Kg = g_kh + (size_t)h * LTOK * HDIM;
    const __half* Vg = g_vh + (size_t)h * LTOK * HDIM;

    uint32_t qf[8][4];
    {
        const __half* q0 = g_qh + ((size_t)h * LTOK + qb + w * 16 + gp) * HDIM;
        const __half* q1 = q0 + 8 * HDIM;
#pragma unroll
        for (int ks = 0; ks < 8; ++ks) {
            int c = ks * 16 + 2 * qd;
            qf[ks][0] = *(const uint32_t*)(q0 + c);
            qf[ks][1] = *(const uint32_t*)(q1 + c);
            qf[ks][2] = *(const uint32_t*)(q0 + c + 8);
            qf[ks][3] = *(const uint32_t*)(q1 + c + 8);
        }
    }

    float ofr[16][4] = {};
    float m0 = -1e30f, m1 = -1e30f, l0 = 0.f, l1 = 0.f;

    load_kv(kbase0, vbase0, Kg, Vg, 0, tid);
    asm volatile("cp.async.commit_group;" ::: "memory");

    const int nT = LTOK / 64;
    for (int t = 0; t < nT; ++t) {
        const int buf = t & 1;
        asm volatile("cp.async.wait_group 0;" ::: "memory");
        __syncthreads();
        if (t + 1 < nT)
            load_kv(kbase0 + (buf ^ 1) * KVBUF, vbase0 + (buf ^ 1) * KVBUF,
                    Kg, Vg, (t + 1) * 64, tid);
        asm volatile("cp.async.commit_group;" ::: "memory");

        const uint32_t kb = kbase0 + buf * KVBUF;
        const uint32_t vb = vbase0 + buf * KVBUF;

        float sfr[8][4] = {};
#pragma unroll
        for (int nt = 0; nt < 8; ++nt) {
            uint32_t bb[8][2];
#pragma unroll
            for (int j = 0; j < 4; ++j) {
                uint32_t ad = kb + (uint32_t)(((nt * 8 + (lane & 7)) * KSH +
                                               j * 32 + (lane >> 3) * 8) * 2);
                uint32_t r[4];
                ldsm4(r, ad);
                bb[2 * j][0] = r[0]; bb[2 * j][1] = r[1];
                bb[2 * j + 1][0] = r[2]; bb[2 * j + 1][1] = r[3];
            }
#pragma unroll
            for (int ks = 0; ks < 8; ++ks)
                mma_f16(sfr[nt], qf[ks], bb[ks][0], bb[ks][1]);
        }

        float mx0 = -1e30f, mx1 = -1e30f;
#pragma unroll
        for (int nt = 0; nt < 8; ++nt) {
            mx0 = fmaxf(mx0, fmaxf(sfr[nt][0], sfr[nt][1]));
            mx1 = fmaxf(mx1, fmaxf(sfr[nt][2], sfr[nt][3]));
        }
        mx0 = fmaxf(mx0, __shfl_xor_sync(0xffffffffu, mx0, 1));
        mx0 = fmaxf(mx0, __shfl_xor_sync(0xffffffffu, mx0, 2));
        mx1 = fmaxf(mx1, __shfl_xor_sync(0xffffffffu, mx1, 1));
        mx1 = fmaxf(mx1, __shfl_xor_sync(0xffffffffu, mx1, 2));
        float mn0 = fmaxf(m0, mx0), mn1 = fmaxf(m1, mx1);
        float a0 = exp2f(m0 - mn0), a1 = exp2f(m1 - mn1);
        m0 = mn0; m1 = mn1;

        float rs0 = 0.f, rs1 = 0.f;
#pragma unroll
        for (int nt = 0; nt < 8; ++nt) {
            sfr[nt][0] = exp2f(sfr[nt][0] - mn0);
            sfr[nt][1] = exp2f(sfr[nt][1] - mn0);
            sfr[nt][2] = exp2f(sfr[nt][2] - mn1);
            sfr[nt][3] = exp2f(sfr[nt][3] - mn1);
            rs0 += sfr[nt][0] + sfr[nt][1];
            rs1 += sfr[nt][2] + sfr[nt][3];
        }
        rs0 += __shfl_xor_sync(0xffffffffu, rs0, 1);
        rs0 += __shfl_xor_sync(0xffffffffu, rs0, 2);
        rs1 += __shfl_xor_sync(0xffffffffu, rs1, 1);
        rs1 += __shfl_xor_sync(0xffffffffu, rs1, 2);
        l0 = l0 * a0 + rs0;
        l1 = l1 * a1 + rs1;

        uint32_t pf[4][4];
#pragma unroll
        for (int ks2 = 0; ks2 < 4; ++ks2) {
            pf[ks2][0] = packh2(sfr[2 * ks2][0], sfr[2 * ks2][1]);
            pf[ks2][1] = packh2(sfr[2 * ks2][2], sfr[2 * ks2][3]);
            pf[ks2][2] = packh2(sfr[2 * ks2 + 1][0], sfr[2 * ks2 + 1][1]);
            pf[ks2][3] = packh2(sfr[2 * ks2 + 1][2], sfr[2 * ks2 + 1][3]);
        }

#pragma unroll
        for (int nt = 0; nt < 16; ++nt) {
            ofr[nt][0] *= a0; ofr[nt][1] *= a0;
            ofr[nt][2] *= a1; ofr[nt][3] *= a1;
        }

#pragma unroll
        for (int nt2 = 0; nt2 < 8; ++nt2) {
#pragma unroll
            for (int ks2 = 0; ks2 < 4; ++ks2) {
                uint32_t ad = vb + (uint32_t)(((ks2 * 16 + (lane & 15)) * KSH +
                                               (2 * nt2 + (lane >> 4)) * 8) * 2);
                uint32_t r[4];
                ldsm4t(r, ad);
                mma_f16(ofr[2 * nt2], pf[ks2], r[0], r[1]);
                mma_f16(ofr[2 * nt2 + 1], pf[ks2], r[2], r[3]);
            }
        }
    }

    float inv0 = 1.0f / l0, inv1 = 1.0f / l1;
    __half* o0 = g_cath + (size_t)(qb + w * 16 + gp) * K2 + h * HDIM;
    __half* o1 = o0 + (size_t)8 * K2;
#pragma unroll
    for (int nt = 0; nt < 16; ++nt) {
        int c = nt * 8 + 2 * qd;
        *(uint32_t*)(o0 + c) = packh2(ofr[nt][0] * inv0, ofr[nt][1] * inv0);
        *(uint32_t*)(o1 + c) = packh2(ofr[nt][2] * inv1, ofr[nt][3] * inv1);
    }
}

// ---------------------------------------------------------------------------
// launch: GEMM1 split qkv/mlp. main: pre -> G1qkv -> flash -> G2b.
// side: w1cvt -> w2cvt -> (after G1qkv) G1mlp -> G2a. flash overlaps G1mlp+G2a.
// ---------------------------------------------------------------------------
extern "C" void kernel_launch(void* const* d_in, const int* in_sizes, int n_in,
                              void* d_out, int out_size) {
    const float* x   = (const float*)d_in[0];
    const float* vec = (const float*)d_in[1];
    const float* pe  = (const float*)d_in[2];
    const float* w1  = (const float*)d_in[3];
    const float* b1  = (const float*)d_in[4];
    const float* w2  = (const float*)d_in[5];
    const float* b2  = (const float*)d_in[6];
    const float* mw  = (const float*)d_in[7];
    const float* mb  = (const float*)d_in[8];
    const float* qsc = (const float*)d_in[9];
    const float* ksc = (const float*)d_in[10];
    float* out = (float*)d_out;

    __half *p_xmodh, *p_cath, *p_w1h, *p_w2h;
    float *p_m, *p_out1;
    cudaGetSymbolAddress((void**)&p_xmodh, g_xmodh);
    cudaGetSymbolAddress((void**)&p_cath, g_cath);
    cudaGetSymbolAddress((void**)&p_m, g_m);
    cudaGetSymbolAddress((void**)&p_w1h, g_w1h);
    cudaGetSymbolAddress((void**)&p_w2h, g_w2h);
    cudaGetSymbolAddress((void**)&p_out1, g_out1);

    cudaFuncSetAttribute(flash_h, cudaFuncAttributeMaxDynamicSharedMemorySize, FL_SMEM);
    cudaFuncSetAttribute(mm_gemm<0>, cudaFuncAttributeMaxDynamicSharedMemorySize, GEMM_SMEM);
    cudaFuncSetAttribute(mm_gemm<2>, cudaFuncAttributeMaxDynamicSharedMemorySize, GEMM_SMEM);
    cudaFuncSetAttribute(mm_gemm<3>, cudaFuncAttributeMaxDynamicSharedMemorySize, GEMM_SMEM);

    cudaStream_t s2;
    cudaStreamCreateWithFlags(&s2, cudaStreamNonBlocking);
    cudaEvent_t e0, e1, e3, e4;
    cudaEventCreateWithFlags(&e0, cudaEventDisableTiming);
    cudaEventCreateWithFlags(&e1, cudaEventDisableTiming);
    cudaEventCreateWithFlags(&e3, cudaEventDisableTiming);
    cudaEventCreateWithFlags(&e4, cudaEventDisableTiming);

    cudaEventRecord(e0, 0);
    cudaStreamWaitEvent(s2, e0, 0);

    // side stream: weight conversions
    cvt_h_k<<<(W1_N4 + 255) / 256, 256, 0, s2>>>(w1, p_w1h, W1_N4);
    cudaEventRecord(e1, s2);
    cvt_h_k<<<(W2_N4 + 255) / 256, 256, 0, s2>>>(w2, p_w2h, W2_N4);

    // main stream: preamble
    silu_k<<<(DMODEL + 255) / 256, 256>>>(vec);
    mod_gemv<<<(3 * DMODEL) / 8, 256>>>(mw, mb);
    ln_mod<<<LTOK, 256>>>(x);

    cudaStreamWaitEvent(0, e1, 0);

    // GEMM1-qkv (main): columns [0, QKVW)
    mm_gemm<0><<<dim3(LTOK / BM, QKVW / BN), GTHREADS, GEMM_SMEM>>>(
        p_xmodh, p_w1h, nullptr, N1, DMODEL, DMODEL, DMODEL, 0,
        b1, nullptr, nullptr, nullptr, pe, qsc, ksc);
    cudaEventRecord(e3, 0);

    // side stream: GEMM1-mlp (columns [QKVW, N1)) then GEMM2a, overlapping flash
    cudaStreamWaitEvent(s2, e3, 0);
    mm_gemm<0><<<dim3(LTOK / BM, MLPD / BN), GTHREADS, GEMM_SMEM, s2>>>(
        p_xmodh, p_w1h, nullptr, N1, DMODEL, DMODEL, DMODEL, QKVW,
        b1, nullptr, nullptr, nullptr, pe, qsc, ksc);
    mm_gemm<2><<<dim3(LTOK / BM, DMODEL / BN), GTHREADS, GEMM_SMEM, s2>>>(
        p_cath + DMODEL, p_w2h + DMODEL, p_out1, DMODEL, MLPD, K2, K2, 0,
        b2, nullptr, nullptr, nullptr, nullptr, nullptr, nullptr);
    cudaEventRecord(e4, s2);

    // main stream: flash (needs only qkv)
    flash_h<<<dim3(LTOK / 64, NHEAD), FTHREADS, FL_SMEM>>>();

    // join: GEMM2b = attn K-half + partial + residual/gate
    cudaStreamWaitEvent(0, e4, 0);
    mm_gemm<3><<<dim3(LTOK / BM, DMODEL / BN), GTHREADS, GEMM_SMEM>>>(
        p_cath, p_w2h, out, DMODEL, DMODEL, K2, K2, 0,
        nullptr, x, p_m + 2 * DMODEL, p_out1, nullptr, nullptr, nullptr);
}

// round 16
// speedup vs baseline: 1.0163x; 1.0163x over previous
#include <cuda_runtime.h>
#include <cuda_fp16.h>
#include <math.h>
#include <stdint.h>

// ---------------------------------------------------------------------------
// Problem constants (B = 1)
// ---------------------------------------------------------------------------
#define LTOK 4096
#define DMODEL 3072
#define NHEAD 24
#define HDIM 128
#define MLPD 12288
#define N1 (3 * DMODEL + MLPD)   // 21504
#define K2 (DMODEL + MLPD)       // 15360
#define QKVW (3 * DMODEL)        // 9216
#define EPSV 1e-6f
#define SM_SCALE 0.08838834764831843f
#define LOG2E 1.4426950408889634f

// ---------------------------------------------------------------------------
// Scratch
// ---------------------------------------------------------------------------
__device__ float  g_sv[DMODEL];
__device__ float  g_m[3 * DMODEL];
__device__ __half g_xmodh[(size_t)LTOK * DMODEL];
__device__ __half g_qh[(size_t)NHEAD * LTOK * HDIM];   // pre-scaled by SM_SCALE*log2e
__device__ __half g_kh[(size_t)NHEAD * LTOK * HDIM];
__device__ __half g_vh[(size_t)NHEAD * LTOK * HDIM];
__device__ __half g_cath[(size_t)LTOK * K2];           // [attn | gelu(mlp)]
__device__ __half g_w1h[(size_t)N1 * DMODEL];
__device__ __half g_w2h[(size_t)DMODEL * K2];
__device__ float  g_out1[(size_t)LTOK * DMODEL];       // GEMM2a partial (mlp@W2b + b2)

// ---------------------------------------------------------------------------
// helpers
// ---------------------------------------------------------------------------
__device__ __forceinline__ uint32_t smem_u32(const void* p) {
    uint32_t a;
    asm("{ .reg .u64 t; cvta.to.shared.u64 t, %1; cvt.u32.u64 %0, t; }"
        : "=r"(a) : "l"(p));
    return a;
}
__device__ __forceinline__ void cp_async16(uint32_t s, const void* g) {
    asm volatile("cp.async.cg.shared.global [%0], [%1], 16;" :: "r"(s), "l"(g) : "memory");
}
__device__ __forceinline__ void mma_f16(float* c, const uint32_t* a,
                                        uint32_t b0, uint32_t b1) {
    asm volatile(
        "mma.sync.aligned.m16n8k16.row.col.f32.f16.f16.f32 "
        "{%0,%1,%2,%3}, {%4,%5,%6,%7}, {%8,%9}, {%0,%1,%2,%3};"
        : "+f"(c[0]), "+f"(c[1]), "+f"(c[2]), "+f"(c[3])
        : "r"(a[0]), "r"(a[1]), "r"(a[2]), "r"(a[3]), "r"(b0), "r"(b1));
}
__device__ __forceinline__ void ldsm4(uint32_t* r, uint32_t addr) {
    asm volatile("ldmatrix.sync.aligned.m8n8.x4.shared.b16 {%0,%1,%2,%3}, [%4];"
                 : "=r"(r[0]), "=r"(r[1]), "=r"(r[2]), "=r"(r[3]) : "r"(addr));
}
__device__ __forceinline__ void ldsm4t(uint32_t* r, uint32_t addr) {
    asm volatile("ldmatrix.sync.aligned.m8n8.x4.trans.shared.b16 {%0,%1,%2,%3}, [%4];"
                 : "=r"(r[0]), "=r"(r[1]), "=r"(r[2]), "=r"(r[3]) : "r"(addr));
}
__device__ __forceinline__ uint32_t packh2(float lo, float hi) {
    __half2 h = __floats2half2_rn(lo, hi);
    return *reinterpret_cast<uint32_t*>(&h);
}
__device__ __forceinline__ float gelu_t(float x) {
    return 0.5f * x * (1.0f + tanhf(0.7978845608028654f * (x + 0.044715f * x * x * x)));
}

// ---------------------------------------------------------------------------
// small kernels
// ---------------------------------------------------------------------------
__global__ void silu_k(const float* __restrict__ vec) {
    int i = blockIdx.x * blockDim.x + threadIdx.x;
    if (i < DMODEL) {
        float v = vec[i];
        g_sv[i] = v / (1.0f + expf(-v));
    }
}

// one warp per output, float4 loads (DRAM-issue limited before)
__global__ void mod_gemv(const float* __restrict__ mw, const float* __restrict__ mb) {
    int j = blockIdx.x * 8 + (threadIdx.x >> 5);
    int lane = threadIdx.x & 31;
    const float4* wr = (const float4*)(mw + (size_t)j * DMODEL);
    const float4* sv = (const float4*)g_sv;
    float s = 0.f;
#pragma unroll 6
    for (int k = lane; k < DMODEL / 4; k += 32) {
        float4 w = wr[k], v = sv[k];
        s += w.x * v.x + w.y * v.y + w.z * v.z + w.w * v.w;
    }
#pragma unroll
    for (int o = 16; o; o >>= 1) s += __shfl_down_sync(0xffffffffu, s, o);
    if (lane == 0) g_m[j] = s + mb[j];
}

__device__ __forceinline__ float block_sum256(float v, float* buf) {
#pragma unroll
    for (int o = 16; o; o >>= 1) v += __shfl_down_sync(0xffffffffu, v, o);
    int w = threadIdx.x >> 5;
    if ((threadIdx.x & 31) == 0) buf[w] = v;
    __syncthreads();
    float s = 0.f;
#pragma unroll
    for (int i = 0; i < 8; i++) s += buf[i];
    return s;
}

__global__ void __launch_bounds__(256) ln_mod(const float* __restrict__ x) {
    __shared__ float xs[DMODEL];
    __shared__ float rbuf[8];
    int row = blockIdx.x;
    const float4* xr = (const float4*)(x + (size_t)row * DMODEL);
    float s = 0.f;
#pragma unroll
    for (int i = threadIdx.x; i < DMODEL / 4; i += 256) {
        float4 v = xr[i];
        ((float4*)xs)[i] = v;
        s += v.x + v.y + v.z + v.w;
    }
    float mu = block_sum256(s, rbuf) * (1.0f / DMODEL);
    __syncthreads();
    float s2 = 0.f;
#pragma unroll
    for (int i = threadIdx.x; i < DMODEL / 4; i += 256) {
        float4 v = ((const float4*)xs)[i];
        float d0 = v.x - mu, d1 = v.y - mu, d2 = v.z - mu, d3 = v.w - mu;
        s2 += d0 * d0 + d1 * d1 + d2 * d2 + d3 * d3;
    }
    float var = block_sum256(s2, rbuf) * (1.0f / DMODEL);
    float rstd = rsqrtf(var + EPSV);
    __half* xm = g_xmodh + (size_t)row * DMODEL;
#pragma unroll
    for (int i = threadIdx.x; i < DMODEL / 4; i += 256) {
        float4 v = ((const float4*)xs)[i];
        float4 sc = ((const float4*)(g_m + DMODEL))[i];
        float4 sh = ((const float4*)g_m)[i];
        float n0 = (v.x - mu) * rstd, n1 = (v.y - mu) * rstd;
        float n2 = (v.z - mu) * rstd, n3 = (v.w - mu) * rstd;
        uint2 u = make_uint2(packh2((1.0f + sc.x) * n0 + sh.x,
                                    (1.0f + sc.y) * n1 + sh.y),
                             packh2((1.0f + sc.z) * n2 + sh.z,
                                    (1.0f + sc.w) * n3 + sh.w));
        *(uint2*)(xm + i * 4) = u;
    }
}

// fp32 -> fp16 weight conversion
#define W1_N4 ((N1 * DMODEL) / 4)
#define W2_N4 ((DMODEL * K2) / 4)
__global__ void __launch_bounds__(256) cvt_h_k(const float* __restrict__ src,
                                               __half* __restrict__ dst, int n4) {
    int i = blockIdx.x * 256 + threadIdx.x;
    if (i < n4) {
        float4 v = ((const float4*)src)[i];
        uint2 u = make_uint2(packh2(v.x, v.y), packh2(v.z, v.w));
        *(uint2*)(dst + (size_t)i * 4) = u;
    }
}

// ---------------------------------------------------------------------------
// fp16 mma.sync GEMM (NT): CTA tile 128x128, 4 warps (2x2), warp tile 64x64.
// 2 CTAs/SM. BK=32, 3-stage cp.async, ldmatrix, 1 sync/chunk. lda/ldb allow
// sub-K GEMMs; bn0 offsets the column-block base for sub-N launches.
// EPI==0: GEMM1 fused epilogue (q/k rmsnorm+rope, v relayout, mlp gelu)
// EPI==2: GEMM2a -> C = acc + bias            (fp32 partial)
// EPI==3: GEMM2b -> C = xres + gate * (partial + acc)
// ---------------------------------------------------------------------------
#define BM 128
#define BN 128
#define BK 32
#define NSTG 3
#define AROWH 40
#define TILEH (BM * AROWH)
#define TILEB (TILEH * 2)                 // 10240 B
#define GEMM_SMEM (NSTG * 2 * TILEB)      // 61440 B
#define GTHREADS 128

__device__ __forceinline__ void ld_stage(uint32_t As, uint32_t Bs,
                                         const __half* __restrict__ Ag,
                                         const __half* __restrict__ Bg,
                                         int lda, int ldb, int kb, int tid) {
#pragma unroll
    for (int it = 0; it < 4; ++it) {
        int id = it * GTHREADS + tid;
        int row = id >> 2, c = id & 3;
        uint32_t off = (uint32_t)(row * AROWH * 2 + c * 16);
        cp_async16(As + off, Ag + (size_t)row * lda + kb + c * 8);
        cp_async16(Bs + off, Bg + (size_t)row * ldb + kb + c * 8);
    }
}

template <int EPI>
__global__ void __launch_bounds__(GTHREADS, 2)
mm_gemm(const __half* __restrict__ A, const __half* __restrict__ B,
        float* __restrict__ C, int Nt, int K, int lda, int ldb, int bn0,
        const float* __restrict__ bias,
        const float* __restrict__ xres, const float* __restrict__ gate,
        const float* __restrict__ partial,
        const float* __restrict__ pe,
        const float* __restrict__ q_scale, const float* __restrict__ k_scale) {
    extern __shared__ __half smh[];
    const uint32_t sA = smem_u32(smh);
    const uint32_t sB = sA + NSTG * TILEB;

    const int tid = threadIdx.x;
    const int wid = tid >> 5, lane = tid & 31;
    const int gp = lane >> 2, qd = lane & 3;
    const int warpM = (wid >> 1) * 64;
    const int warpN = (wid & 1) * 64;
    const int bm = blockIdx.x * BM;
    const int bn = blockIdx.y * BN + bn0;

    const __half* Ag = A + (size_t)bm * lda;
    const __half* Bg = B + (size_t)bn * ldb;
    const int nch = K / BK;

    float acc[4][8][4] = {};

#pragma unroll
    for (int p = 0; p < NSTG - 1; ++p) {
        ld_stage(sA + p * TILEB, sB + p * TILEB, Ag, Bg, lda, ldb, p * BK, tid);
        asm volatile("cp.async.commit_group;" ::: "memory");
    }

    const uint32_t aOff = (uint32_t)((warpM + (lane & 15)) * AROWH + (lane >> 4) * 8) * 2;
    const uint32_t bOff = (uint32_t)((warpN + (lane & 7)) * AROWH + (lane >> 3) * 8) * 2;

    for (int j = 0; j < nch; ++j) {
        asm volatile("cp.async.wait_group %0;" :: "n"(NSTG - 2) : "memory");
        __syncthreads();
        const int c = j + NSTG - 1;
        if (c < nch) {
            const int st = c % NSTG;
            ld_stage(sA + st * TILEB, sB + st * TILEB, Ag, Bg, lda, ldb, c * BK, tid);
        }
        asm volatile("cp.async.commit_group;" ::: "memory");

        const uint32_t asb = sA + (j % NSTG) * TILEB + aOff;
        const uint32_t bsb = sB + (j % NSTG) * TILEB + bOff;

        uint32_t bf[8][4];
#pragma unroll
        for (int nt = 0; nt < 8; ++nt)
            ldsm4(bf[nt], bsb + (uint32_t)(nt * 8 * AROWH) * 2);

#pragma unroll
        for (int ks = 0; ks < 2; ++ks) {
            uint32_t af[4][4];
#pragma unroll
            for (int mt = 0; mt < 4; ++mt)
                ldsm4(af[mt], asb + (uint32_t)(mt * 16 * AROWH + ks * 16) * 2);
#pragma unroll
            for (int mt = 0; mt < 4; ++mt)
#pragma unroll
                for (int nt = 0; nt < 8; ++nt)
                    mma_f16(acc[mt][nt], af[mt], bf[nt][2 * ks], bf[nt][2 * ks + 1]);
        }
    }

    // epilogue
    if (EPI == 0) {
        const int btype = bn / DMODEL;     // 0=q, 1=k, 2=v, >=3 mlp
        if (btype >= 3) {
#pragma unroll
            for (int nt = 0; nt < 8; ++nt) {
                const int col = bn + warpN + nt * 8 + 2 * qd;
                const float b0 = bias[col], b1v = bias[col + 1];
#pragma unroll
                for (int mt = 0; mt < 4; ++mt) {
#pragma unroll
                    for (int h2 = 0; h2 < 2; ++h2) {
                        const int row = bm + warpM + mt * 16 + gp + h2 * 8;
                        float v0 = acc[mt][nt][h2 * 2 + 0] + b0;
                        float v1 = acc[mt][nt][h2 * 2 + 1] + b1v;
                        *(uint32_t*)(g_cath + (size_t)row * K2 + (col - 2 * DMODEL)) =
                            packh2(gelu_t(v0), gelu_t(v1));
                    }
                }
            }
        } else {
            const int hh = (bn % DMODEL) >> 7;
            float ssp[4][2] = {};
#pragma unroll
            for (int nt = 0; nt < 8; ++nt) {
                const int col = bn + warpN + nt * 8 + 2 * qd;
                const float b0 = bias[col], b1v = bias[col + 1];
#pragma unroll
                for (int mt = 0; mt < 4; ++mt)
#pragma unroll
                    for (int h2 = 0; h2 < 2; ++h2) {
                        float v0 = acc[mt][nt][h2 * 2 + 0] + b0;
                        float v1 = acc[mt][nt][h2 * 2 + 1] + b1v;
                        acc[mt][nt][h2 * 2 + 0] = v0;
                        acc[mt][nt][h2 * 2 + 1] = v1;
                        if (btype < 2) ssp[mt][h2] += v0 * v0 + v1 * v1;
                    }
            }
            if (btype == 2) {
#pragma unroll
                for (int mt = 0; mt < 4; ++mt)
#pragma unroll
                    for (int h2 = 0; h2 < 2; ++h2) {
                        const int grow = bm + warpM + mt * 16 + gp + h2 * 8;
#pragma unroll
                        for (int nt = 0; nt < 8; ++nt) {
                            const int c0 = warpN + nt * 8 + 2 * qd;
                            *(uint32_t*)(g_vh + ((size_t)hh * LTOK + grow) * HDIM + c0) =
                                packh2(acc[mt][nt][h2 * 2 + 0], acc[mt][nt][h2 * 2 + 1]);
                        }
                    }
            } else {
#pragma unroll
                for (int mt = 0; mt < 4; ++mt)
#pragma unroll
                    for (int h2 = 0; h2 < 2; ++h2) {
                        ssp[mt][h2] += __shfl_xor_sync(0xffffffffu, ssp[mt][h2], 1);
                        ssp[mt][h2] += __shfl_xor_sync(0xffffffffu, ssp[mt][h2], 2);
                    }
                float* red = (float*)smh;
                __syncthreads();
                if (qd == 0) {
#pragma unroll
                    for (int mt = 0; mt < 4; ++mt)
#pragma unroll
                        for (int h2 = 0; h2 < 2; ++h2)
                            red[(warpM + mt * 16 + gp + h2 * 8) * 2 + (warpN >> 6)] =
                                ssp[mt][h2];
                }
                __syncthreads();
                const float* sc = (btype == 0) ? q_scale : k_scale;
                __half* dst = (btype == 0) ? g_qh : g_kh;
                const float fin = (btype == 0) ? SM_SCALE * LOG2E : 1.0f;
#pragma unroll
                for (int mt = 0; mt < 4; ++mt)
#pragma unroll
                    for (int h2 = 0; h2 < 2; ++h2) {
                        const int lrow = warpM + mt * 16 + gp + h2 * 8;
                        const float ss = red[lrow * 2 + 0] + red[lrow * 2 + 1];
                        const float rstd = rsqrtf(ss * (1.0f / HDIM) + EPSV);
                        const int grow = bm + lrow;
#pragma unroll
                        for (int nt = 0; nt < 8; ++nt) {
                            const int c0 = warpN + nt * 8 + 2 * qd;
                            float v0 = acc[mt][nt][h2 * 2 + 0] * rstd * sc[c0];
                            float v1 = acc[mt][nt][h2 * 2 + 1] * rstd * sc[c0 + 1];
                            float4 f = *(const float4*)(pe +
                                ((size_t)grow * (HDIM / 2) + (c0 >> 1)) * 4);
                            float o0 = f.x * v0 + f.y * v1;
                            float o1 = f.z * v0 + f.w * v1;
                            *(uint32_t*)(dst + ((size_t)hh * LTOK + grow) * HDIM + c0) =
                                packh2(o0 * fin, o1 * fin);
                        }
                    }
            }
        }
    } else if (EPI == 2) {
#pragma unroll
        for (int nt = 0; nt < 8; ++nt) {
            const int col = bn + warpN + nt * 8 + 2 * qd;
            const float b0 = bias[col], b1v = bias[col + 1];
#pragma unroll
            for (int mt = 0; mt < 4; ++mt) {
#pragma unroll
                for (int h2 = 0; h2 < 2; ++h2) {
                    const int row = bm + warpM + mt * 16 + gp + h2 * 8;
                    const size_t off = (size_t)row * Nt + col;
                    *(float2*)(C + off) = make_float2(acc[mt][nt][h2 * 2 + 0] + b0,
                                                      acc[mt][nt][h2 * 2 + 1] + b1v);
                }
            }
        }
    } else {
#pragma unroll
        for (int nt = 0; nt < 8; ++nt) {
            const int col = bn + warpN + nt * 8 + 2 * qd;
            const float g0 = gate[col], g1 = gate[col + 1];
#pragma unroll
            for (int mt = 0; mt < 4; ++mt) {
#pragma unroll
                for (int h2 = 0; h2 < 2; ++h2) {
                    const int row = bm + warpM + mt * 16 + gp + h2 * 8;
                    const size_t off = (size_t)row * Nt + col;
                    float2 xr = *(const float2*)(xres + off);
                    float2 pp = *(const float2*)(partial + off);
                    float v0 = xr.x + g0 * (pp.x + acc[mt][nt][h2 * 2 + 0]);
                    float v1 = xr.y + g1 * (pp.y + acc[mt][nt][h2 * 2 + 1]);
                    *(float2*)(C + off) = make_float2(v0, v1);
                }
            }
        }
    }
}

// ---------------------------------------------------------------------------
// Flash attention fp16 mma: Q tile 64, 128 threads, 2 CTAs/SM (R13 validated)
// ---------------------------------------------------------------------------
#define KSH 136
#define KVBUF (64 * KSH * 2)
#define FL_SMEM (4 * KVBUF)
#define FTHREADS 128

__device__ __forceinline__ void load_kv(uint32_t kd, uint32_t vd,
                                        const __half* __restrict__ Kg,
                                        const __half* __restrict__ Vg,
                                        int kt, int tid) {
#pragma unroll
    for (int it = 0; it < 8; ++it) {
        int id = it * FTHREADS + tid;
        int row = id >> 4, c = id & 15;
        uint32_t off = (uint32_t)(row * KSH * 2 + c * 16);
        const size_t goff = (size_t)(kt + row) * HDIM + c * 8;
        cp_async16(kd + off, Kg + goff);
        cp_async16(vd + off, Vg + goff);
    }
}

__global__ void __launch_bounds__(FTHREADS, 2) flash_h() {
    extern __shared__ __half smh[];
    const uint32_t kbase0 = smem_u32(smh);
    const uint32_t vbase0 = kbase0 + 2 * KVBUF;

    const int h = blockIdx.y;
    const int qb = blockIdx.x * 64;
    const int tid = threadIdx.x;
    const int w = tid >> 5, lane = tid & 31;
    const int gp = lane >> 2, qd = lane & 3;

    const __half* Kg = g_kh + (size_t)h * LTOK * HDIM;
    const __half* Vg = g_vh + (size_t)h * LTOK * HDIM;

    uint32_t qf[8][4];
    {
        const __half* q0 = g_qh + ((size_t)h * LTOK + qb + w * 16 + gp) * HDIM;
        const __half* q1 = q0 + 8 * HDIM;
#pragma unroll
        for (int ks = 0; ks < 8; ++ks) {
            int c = ks * 16 + 2 * qd;
            qf[ks][0] = *(const uint32_t*)(q0 + c);
            qf[ks][1] = *(const uint32_t*)(q1 + c);
            qf[ks][2] = *(const uint32_t*)(q0 + c + 8);
            qf[ks][3] = *(const uint32_t*)(q1 + c + 8);
        }
    }

    float ofr[16][4] = {};
    float m0 = -1e30f, m1 = -1e30f, l0 = 0.f, l1 = 0.f;

    load_kv(kbase0, vbase0, Kg, Vg, 0, tid);
    asm volatile("cp.async.commit_group;" ::: "memory");

    const int nT = LTOK / 64;
    for (int t = 0; t < nT; ++t) {
        const int buf = t & 1;
        asm volatile("cp.async.wait_group 0;" ::: "memory");
        __syncthreads();
        if (t + 1 < nT)
            load_kv(kbase0 + (buf ^ 1) * KVBUF, vbase0 + (buf ^ 1) * KVBUF,
                    Kg, Vg, (t + 1) * 64, tid);
        asm volatile("cp.async.commit_group;" ::: "memory");

        const uint32_t kb = kbase0 + buf * KVBUF;
        const uint32_t vb = vbase0 + buf * KVBUF;

        float sfr[8][4] = {};
#pragma unroll
        for (int nt = 0; nt < 8; ++nt) {
            uint32_t bb[8][2];
#pragma unroll
            for (int j = 0; j < 4; ++j) {
                uint32_t ad = kb + (uint32_t)(((nt * 8 + (lane & 7)) * KSH +
                                               j * 32 + (lane >> 3) * 8) * 2);
                uint32_t r[4];
                ldsm4(r, ad);
                bb[2 * j][0] = r[0]; bb[2 * j][1] = r[1];
                bb[2 * j + 1][0] = r[2]; bb[2 * j + 1][1] = r[3];
            }
#pragma unroll
            for (int ks = 0; ks < 8; ++ks)
                mma_f16(sfr[nt], qf[ks], bb[ks][0], bb[ks][1]);
        }

        float mx0 = -1e30f, mx1 = -1e30f;
#pragma unroll
        for (int nt = 0; nt < 8; ++nt) {
            mx0 = fmaxf(mx0, fmaxf(sfr[nt][0], sfr[nt][1]));
            mx1 = fmaxf(mx1, fmaxf(sfr[nt][2], sfr[nt][3]));
        }
        mx0 = fmaxf(mx0, __shfl_xor_sync(0xffffffffu, mx0, 1));
        mx0 = fmaxf(mx0, __shfl_xor_sync(0xffffffffu, mx0, 2));
        mx1 = fmaxf(mx1, __shfl_xor_sync(0xffffffffu, mx1, 1));
        mx1 = fmaxf(mx1, __shfl_xor_sync(0xffffffffu, mx1, 2));
        float mn0 = fmaxf(m0, mx0), mn1 = fmaxf(m1, mx1);
        float a0 = exp2f(m0 - mn0), a1 = exp2f(m1 - mn1);
        m0 = mn0; m1 = mn1;

        float rs0 = 0.f, rs1 = 0.f;
#pragma unroll
        for (int nt = 0; nt < 8; ++nt) {
            sfr[nt][0] = exp2f(sfr[nt][0] - mn0);
            sfr[nt][1] = exp2f(sfr[nt][1] - mn0);
            sfr[nt][2] = exp2f(sfr[nt][2] - mn1);
            sfr[nt][3] = exp2f(sfr[nt][3] - mn1);
            rs0 += sfr[nt][0] + sfr[nt][1];
            rs1 += sfr[nt][2] + sfr[nt][3];
        }
        rs0 += __shfl_xor_sync(0xffffffffu, rs0, 1);
        rs0 += __shfl_xor_sync(0xffffffffu, rs0, 2);
        rs1 += __shfl_xor_sync(0xffffffffu, rs1, 1);
        rs1 += __shfl_xor_sync(0xffffffffu, rs1, 2);
        l0 = l0 * a0 + rs0;
        l1 = l1 * a1 + rs1;

        uint32_t pf[4][4];
#pragma unroll
        for (int ks2 = 0; ks2 < 4; ++ks2) {
            pf[ks2][0] = packh2(sfr[2 * ks2][0], sfr[2 * ks2][1]);
            pf[ks2][1] = packh2(sfr[2 * ks2][2], sfr[2 * ks2][3]);
            pf[ks2][2] = packh2(sfr[2 * ks2 + 1][0], sfr[2 * ks2 + 1][1]);
            pf[ks2][3] = packh2(sfr[2 * ks2 + 1][2], sfr[2 * ks2 + 1][3]);
        }

#pragma unroll
        for (int nt = 0; nt < 16; ++nt) {
            ofr[nt][0] *= a0; ofr[nt][1] *= a0;
            ofr[nt][2] *= a1; ofr[nt][3] *= a1;
        }

#pragma unroll
        for (int nt2 = 0; nt2 < 8; ++nt2) {
#pragma unroll
            for (int ks2 = 0; ks2 < 4; ++ks2) {
                uint32_t ad = vb + (uint32_t)(((ks2 * 16 + (lane & 15)) * KSH +
                                               (2 * nt2 + (lane >> 4)) * 8) * 2);
                uint32_t r[4];
                ldsm4t(r, ad);
                mma_f16(ofr[2 * nt2], pf[ks2], r[0], r[1]);
                mma_f16(ofr[2 * nt2 + 1], pf[ks2], r[2], r[3]);
            }
        }
    }

    float inv0 = 1.0f / l0, inv1 = 1.0f / l1;
    __half* o0 = g_cath + (size_t)(qb + w * 16 + gp) * K2 + h * HDIM;
    __half* o1 = o0 + (size_t)8 * K2;
#pragma unroll
    for (int nt = 0; nt < 16; ++nt) {
        int c = nt * 8 + 2 * qd;
        *(uint32_t*)(o0 + c) = packh2(ofr[nt][0] * inv0, ofr[nt][1] * inv0);
        *(uint32_t*)(o1 + c) = packh2(ofr[nt][2] * inv1, ofr[nt][3] * inv1);
    }
}

// ---------------------------------------------------------------------------
// launch (R14 schedule -- best validated): side stream carries weight cvt and
// GEMM2a (mlp K-half of GEMM2), overlapping flash. GEMM2b joins and finishes.
// ---------------------------------------------------------------------------
extern "C" void kernel_launch(void* const* d_in, const int* in_sizes, int n_in,
                              void* d_out, int out_size) {
    const float* x   = (const float*)d_in[0];
    const float* vec = (const float*)d_in[1];
    const float* pe  = (const float*)d_in[2];
    const float* w1  = (const float*)d_in[3];
    const float* b1  = (const float*)d_in[4];
    const float* w2  = (const float*)d_in[5];
    const float* b2  = (const float*)d_in[6];
    const float* mw  = (const float*)d_in[7];
    const float* mb  = (const float*)d_in[8];
    const float* qsc = (const float*)d_in[9];
    const float* ksc = (const float*)d_in[10];
    float* out = (float*)d_out;

    __half *p_xmodh, *p_cath, *p_w1h, *p_w2h;
    float *p_m, *p_out1;
    cudaGetSymbolAddress((void**)&p_xmodh, g_xmodh);
    cudaGetSymbolAddress((void**)&p_cath, g_cath);
    cudaGetSymbolAddress((void**)&p_m, g_m);
    cudaGetSymbolAddress((void**)&p_w1h, g_w1h);
    cudaGetSymbolAddress((void**)&p_w2h, g_w2h);
    cudaGetSymbolAddress((void**)&p_out1, g_out1);

    cudaFuncSetAttribute(flash_h, cudaFuncAttributeMaxDynamicSharedMemorySize, FL_SMEM);
    cudaFuncSetAttribute(mm_gemm<0>, cudaFuncAttributeMaxDynamicSharedMemorySize, GEMM_SMEM);
    cudaFuncSetAttribute(mm_gemm<2>, cudaFuncAttributeMaxDynamicSharedMemorySize, GEMM_SMEM);
    cudaFuncSetAttribute(mm_gemm<3>, cudaFuncAttributeMaxDynamicSharedMemorySize, GEMM_SMEM);

    cudaStream_t s2;
    cudaStreamCreateWithFlags(&s2, cudaStreamNonBlocking);
    cudaEvent_t e0, e1, e3, e4;
    cudaEventCreateWithFlags(&e0, cudaEventDisableTiming);
    cudaEventCreateWithFlags(&e1, cudaEventDisableTiming);
    cudaEventCreateWithFlags(&e3, cudaEventDisableTiming);
    cudaEventCreateWithFlags(&e4, cudaEventDisableTiming);

    cudaEventRecord(e0, 0);
    cudaStreamWaitEvent(s2, e0, 0);

    // side stream: weight conversions
    cvt_h_k<<<(W1_N4 + 255) / 256, 256, 0, s2>>>(w1, p_w1h, W1_N4);
    cudaEventRecord(e1, s2);
    cvt_h_k<<<(W2_N4 + 255) / 256, 256, 0, s2>>>(w2, p_w2h, W2_N4);

    // main stream: preamble
    silu_k<<<(DMODEL + 255) / 256, 256>>>(vec);
    mod_gemv<<<(3 * DMODEL) / 8, 256>>>(mw, mb);
    ln_mod<<<LTOK, 256>>>(x);

    cudaStreamWaitEvent(0, e1, 0);

    // GEMM1 fused (main, full width)
    mm_gemm<0><<<dim3(LTOK / BM, N1 / BN), GTHREADS, GEMM_SMEM>>>(
        p_xmodh, p_w1h, nullptr, N1, DMODEL, DMODEL, DMODEL, 0,
        b1, nullptr, nullptr, nullptr, pe, qsc, ksc);
    cudaEventRecord(e3, 0);

    // side stream: GEMM2a (mlp K-half) overlaps flash
    cudaStreamWaitEvent(s2, e3, 0);
    mm_gemm<2><<<dim3(LTOK / BM, DMODEL / BN), GTHREADS, GEMM_SMEM, s2>>>(
        p_cath + DMODEL, p_w2h + DMODEL, p_out1, DMODEL, MLPD, K2, K2, 0,
        b2, nullptr, nullptr, nullptr, nullptr, nullptr, nullptr);
    cudaEventRecord(e4, s2);

    // main stream: flash
    flash_h<<<dim3(LTOK / 64, NHEAD), FTHREADS, FL_SMEM>>>();

    // join: GEMM2b = attn K-half + partial + residual/gate
    cudaStreamWaitEvent(0, e4, 0);
    mm_gemm<3><<<dim3(LTOK / BM, DMODEL / BN), GTHREADS, GEMM_SMEM>>>(
        p_cath, p_w2h, out, DMODEL, DMODEL, K2, K2, 0,
        nullptr, x, p_m + 2 * DMODEL, p_out1, nullptr, nullptr, nullptr);
}

// round 17
// speedup vs baseline: 1.0717x; 1.0545x over previous
#include <cuda_runtime.h>
#include <cuda_fp16.h>
#include <math.h>
#include <stdint.h>

// ---------------------------------------------------------------------------
// Problem constants (B = 1)
// ---------------------------------------------------------------------------
#define LTOK 4096
#define DMODEL 3072
#define NHEAD 24
#define HDIM 128
#define MLPD 12288
#define N1 (3 * DMODEL + MLPD)   // 21504
#define K2 (DMODEL + MLPD)       // 15360
#define QKVW (3 * DMODEL)        // 9216
#define EPSV 1e-6f
#define SM_SCALE 0.08838834764831843f
#define LOG2E 1.4426950408889634f

// ---------------------------------------------------------------------------
// Scratch
// ---------------------------------------------------------------------------
__device__ float  g_m[3 * DMODEL];
__device__ __half g_xmodh[(size_t)LTOK * DMODEL];
__device__ __half g_qh[(size_t)NHEAD * LTOK * HDIM];   // pre-scaled by SM_SCALE*log2e
__device__ __half g_kh[(size_t)NHEAD * LTOK * HDIM];
__device__ __half g_vh[(size_t)NHEAD * LTOK * HDIM];
__device__ __half g_cath[(size_t)LTOK * K2];           // [attn | gelu(mlp)]
__device__ __half g_w1h[(size_t)N1 * DMODEL];
__device__ __half g_w2h[(size_t)DMODEL * K2];
__device__ float  g_out1[(size_t)LTOK * DMODEL];       // GEMM2a partial (mlp@W2b + b2)

// ---------------------------------------------------------------------------
// helpers
// ---------------------------------------------------------------------------
__device__ __forceinline__ uint32_t smem_u32(const void* p) {
    uint32_t a;
    asm("{ .reg .u64 t; cvta.to.shared.u64 t, %1; cvt.u32.u64 %0, t; }"
        : "=r"(a) : "l"(p));
    return a;
}
__device__ __forceinline__ void cp_async16(uint32_t s, const void* g) {
    asm volatile("cp.async.cg.shared.global [%0], [%1], 16;" :: "r"(s), "l"(g) : "memory");
}
__device__ __forceinline__ void mma_f16(float* c, const uint32_t* a,
                                        uint32_t b0, uint32_t b1) {
    asm volatile(
        "mma.sync.aligned.m16n8k16.row.col.f32.f16.f16.f32 "
        "{%0,%1,%2,%3}, {%4,%5,%6,%7}, {%8,%9}, {%0,%1,%2,%3};"
        : "+f"(c[0]), "+f"(c[1]), "+f"(c[2]), "+f"(c[3])
        : "r"(a[0]), "r"(a[1]), "r"(a[2]), "r"(a[3]), "r"(b0), "r"(b1));
}
__device__ __forceinline__ void ldsm4(uint32_t* r, uint32_t addr) {
    asm volatile("ldmatrix.sync.aligned.m8n8.x4.shared.b16 {%0,%1,%2,%3}, [%4];"
                 : "=r"(r[0]), "=r"(r[1]), "=r"(r[2]), "=r"(r[3]) : "r"(addr));
}
__device__ __forceinline__ void ldsm4t(uint32_t* r, uint32_t addr) {
    asm volatile("ldmatrix.sync.aligned.m8n8.x4.trans.shared.b16 {%0,%1,%2,%3}, [%4];"
                 : "=r"(r[0]), "=r"(r[1]), "=r"(r[2]), "=r"(r[3]) : "r"(addr));
}
__device__ __forceinline__ uint32_t packh2(float lo, float hi) {
    __half2 h = __floats2half2_rn(lo, hi);
    return *reinterpret_cast<uint32_t*>(&h);
}
__device__ __forceinline__ float gelu_t(float x) {
    return 0.5f * x * (1.0f + tanhf(0.7978845608028654f * (x + 0.044715f * x * x * x)));
}
__device__ __forceinline__ float silu_f(float v) {
    return v / (1.0f + expf(-v));
}

// ---------------------------------------------------------------------------
// small kernels
// ---------------------------------------------------------------------------
// one warp per output; silu folded in; float4 loads
__global__ void mod_gemv(const float* __restrict__ vec,
                         const float* __restrict__ mw, const float* __restrict__ mb) {
    int j = blockIdx.x * 8 + (threadIdx.x >> 5);
    int lane = threadIdx.x & 31;
    const float4* wr = (const float4*)(mw + (size_t)j * DMODEL);
    const float4* sv = (const float4*)vec;
    float s = 0.f;
#pragma unroll 6
    for (int k = lane; k < DMODEL / 4; k += 32) {
        float4 w = wr[k], v = sv[k];
        s += w.x * silu_f(v.x) + w.y * silu_f(v.y) +
             w.z * silu_f(v.z) + w.w * silu_f(v.w);
    }
#pragma unroll
    for (int o = 16; o; o >>= 1) s += __shfl_down_sync(0xffffffffu, s, o);
    if (lane == 0) g_m[j] = s + mb[j];
}

__device__ __forceinline__ float block_sum256(float v, float* buf) {
#pragma unroll
    for (int o = 16; o; o >>= 1) v += __shfl_down_sync(0xffffffffu, v, o);
    int w = threadIdx.x >> 5;
    if ((threadIdx.x & 31) == 0) buf[w] = v;
    __syncthreads();
    float s = 0.f;
#pragma unroll
    for (int i = 0; i < 8; i++) s += buf[i];
    return s;
}

__global__ void __launch_bounds__(256) ln_mod(const float* __restrict__ x) {
    __shared__ float xs[DMODEL];
    __shared__ float rbuf[8];
    int row = blockIdx.x;
    const float4* xr = (const float4*)(x + (size_t)row * DMODEL);
    float s = 0.f;
#pragma unroll
    for (int i = threadIdx.x; i < DMODEL / 4; i += 256) {
        float4 v = xr[i];
        ((float4*)xs)[i] = v;
        s += v.x + v.y + v.z + v.w;
    }
    float mu = block_sum256(s, rbuf) * (1.0f / DMODEL);
    __syncthreads();
    float s2 = 0.f;
#pragma unroll
    for (int i = threadIdx.x; i < DMODEL / 4; i += 256) {
        float4 v = ((const float4*)xs)[i];
        float d0 = v.x - mu, d1 = v.y - mu, d2 = v.z - mu, d3 = v.w - mu;
        s2 += d0 * d0 + d1 * d1 + d2 * d2 + d3 * d3;
    }
    float var = block_sum256(s2, rbuf) * (1.0f / DMODEL);
    float rstd = rsqrtf(var + EPSV);
    __half* xm = g_xmodh + (size_t)row * DMODEL;
#pragma unroll
    for (int i = threadIdx.x; i < DMODEL / 4; i += 256) {
        float4 v = ((const float4*)xs)[i];
        float4 sc = ((const float4*)(g_m + DMODEL))[i];
        float4 sh = ((const float4*)g_m)[i];
        float n0 = (v.x - mu) * rstd, n1 = (v.y - mu) * rstd;
        float n2 = (v.z - mu) * rstd, n3 = (v.w - mu) * rstd;
        uint2 u = make_uint2(packh2((1.0f + sc.x) * n0 + sh.x,
                                    (1.0f + sc.y) * n1 + sh.y),
                             packh2((1.0f + sc.z) * n2 + sh.z,
                                    (1.0f + sc.w) * n3 + sh.w));
        *(uint2*)(xm + i * 4) = u;
    }
}

// fp32 -> fp16 weight conversion
#define W1_N4 ((N1 * DMODEL) / 4)
#define W2_N4 ((DMODEL * K2) / 4)
__global__ void __launch_bounds__(256) cvt_h_k(const float* __restrict__ src,
                                               __half* __restrict__ dst, int n4) {
    int i = blockIdx.x * 256 + threadIdx.x;
    if (i < n4) {
        float4 v = ((const float4*)src)[i];
        uint2 u = make_uint2(packh2(v.x, v.y), packh2(v.z, v.w));
        *(uint2*)(dst + (size_t)i * 4) = u;
    }
}

// ---------------------------------------------------------------------------
// fp16 mma.sync GEMM (NT): CTA tile 128x128, 4 warps (2x2), warp tile 64x64.
// 2 CTAs/SM. BK=64 (two 32-wide halves per chunk), 2-stage cp.async,
// ldmatrix, 1 sync per 64-wide chunk (half the barriers of BK=32).
// lda/ldb allow sub-K GEMMs; bn0 offsets column-block base.
// EPI==0: GEMM1 fused epilogue (q/k rmsnorm+rope, v relayout, mlp gelu)
// EPI==2: GEMM2a -> C = acc + bias            (fp32 partial)
// EPI==3: GEMM2b -> C = xres + gate * (partial + acc)
// ---------------------------------------------------------------------------
#define BM 128
#define BN 128
#define BK 64
#define NSTG 2
#define AROWH 72                          // 64 data halves + 8 pad
#define TILEH (BM * AROWH)
#define TILEB (TILEH * 2)                 // 18432 B
#define GEMM_SMEM (NSTG * 2 * TILEB)      // 73728 B
#define GTHREADS 128

__device__ __forceinline__ void ld_stage(uint32_t As, uint32_t Bs,
                                         const __half* __restrict__ Ag,
                                         const __half* __restrict__ Bg,
                                         int lda, int ldb, int kb, int tid) {
#pragma unroll
    for (int it = 0; it < 8; ++it) {
        int id = it * GTHREADS + tid;         // 1024 16B chunks per operand
        int row = id >> 3, c = id & 7;
        uint32_t off = (uint32_t)(row * AROWH * 2 + c * 16);
        cp_async16(As + off, Ag + (size_t)row * lda + kb + c * 8);
        cp_async16(Bs + off, Bg + (size_t)row * ldb + kb + c * 8);
    }
}

template <int EPI>
__global__ void __launch_bounds__(GTHREADS, 2)
mm_gemm(const __half* __restrict__ A, const __half* __restrict__ B,
        float* __restrict__ C, int Nt, int K, int lda, int ldb, int bn0,
        const float* __restrict__ bias,
        const float* __restrict__ xres, const float* __restrict__ gate,
        const float* __restrict__ partial,
        const float* __restrict__ pe,
        const float* __restrict__ q_scale, const float* __restrict__ k_scale) {
    extern __shared__ __half smh[];
    const uint32_t sA = smem_u32(smh);
    const uint32_t sB = sA + NSTG * TILEB;

    const int tid = threadIdx.x;
    const int wid = tid >> 5, lane = tid & 31;
    const int gp = lane >> 2, qd = lane & 3;
    const int warpM = (wid >> 1) * 64;
    const int warpN = (wid & 1) * 64;
    const int bm = blockIdx.x * BM;
    const int bn = blockIdx.y * BN + bn0;

    const __half* Ag = A + (size_t)bm * lda;
    const __half* Bg = B + (size_t)bn * ldb;
    const int nch = K / BK;

    float acc[4][8][4] = {};

    // prologue: stage 0
    ld_stage(sA, sB, Ag, Bg, lda, ldb, 0, tid);
    asm volatile("cp.async.commit_group;" ::: "memory");

    const uint32_t aOff = (uint32_t)((warpM + (lane & 15)) * AROWH + (lane >> 4) * 8) * 2;
    const uint32_t bOff = (uint32_t)((warpN + (lane & 7)) * AROWH + (lane >> 3) * 8) * 2;

    for (int j = 0; j < nch; ++j) {
        asm volatile("cp.async.wait_group 0;" ::: "memory");   // chunk j resident
        __syncthreads();                                        // prev chunk consumed
        if (j + 1 < nch) {
            const int st = (j + 1) & 1;
            ld_stage(sA + st * TILEB, sB + st * TILEB, Ag, Bg, lda, ldb,
                     (j + 1) * BK, tid);
        }
        asm volatile("cp.async.commit_group;" ::: "memory");

        const uint32_t asb = sA + (j & 1) * TILEB + aOff;
        const uint32_t bsb = sB + (j & 1) * TILEB + bOff;

#pragma unroll
        for (int half = 0; half < 2; ++half) {
            uint32_t bf[8][4];
#pragma unroll
            for (int nt = 0; nt < 8; ++nt)
                ldsm4(bf[nt], bsb + (uint32_t)(nt * 8 * AROWH + half * 32) * 2);
#pragma unroll
            for (int ks = 0; ks < 2; ++ks) {
                uint32_t af[4][4];
#pragma unroll
                for (int mt = 0; mt < 4; ++mt)
                    ldsm4(af[mt], asb + (uint32_t)(mt * 16 * AROWH +
                                                    half * 32 + ks * 16) * 2);
#pragma unroll
                for (int mt = 0; mt < 4; ++mt)
#pragma unroll
                    for (int nt = 0; nt < 8; ++nt)
                        mma_f16(acc[mt][nt], af[mt], bf[nt][2 * ks], bf[nt][2 * ks + 1]);
            }
        }
    }

    // epilogue
    if (EPI == 0) {
        const int btype = bn / DMODEL;     // 0=q, 1=k, 2=v, >=3 mlp
        if (btype >= 3) {
#pragma unroll
            for (int nt = 0; nt < 8; ++nt) {
                const int col = bn + warpN + nt * 8 + 2 * qd;
                const float b0 = bias[col], b1v = bias[col + 1];
#pragma unroll
                for (int mt = 0; mt < 4; ++mt) {
#pragma unroll
                    for (int h2 = 0; h2 < 2; ++h2) {
                        const int row = bm + warpM + mt * 16 + gp + h2 * 8;
                        float v0 = acc[mt][nt][h2 * 2 + 0] + b0;
                        float v1 = acc[mt][nt][h2 * 2 + 1] + b1v;
                        *(uint32_t*)(g_cath + (size_t)row * K2 + (col - 2 * DMODEL)) =
                            packh2(gelu_t(v0), gelu_t(v1));
                    }
                }
            }
        } else {
            const int hh = (bn % DMODEL) >> 7;
            float ssp[4][2] = {};
#pragma unroll
            for (int nt = 0; nt < 8; ++nt) {
                const int col = bn + warpN + nt * 8 + 2 * qd;
                const float b0 = bias[col], b1v = bias[col + 1];
#pragma unroll
                for (int mt = 0; mt < 4; ++mt)
#pragma unroll
                    for (int h2 = 0; h2 < 2; ++h2) {
                        float v0 = acc[mt][nt][h2 * 2 + 0] + b0;
                        float v1 = acc[mt][nt][h2 * 2 + 1] + b1v;
                        acc[mt][nt][h2 * 2 + 0] = v0;
                        acc[mt][nt][h2 * 2 + 1] = v1;
                        if (btype < 2) ssp[mt][h2] += v0 * v0 + v1 * v1;
                    }
            }
            if (btype == 2) {
#pragma unroll
                for (int mt = 0; mt < 4; ++mt)
#pragma unroll
                    for (int h2 = 0; h2 < 2; ++h2) {
                        const int grow = bm + warpM + mt * 16 + gp + h2 * 8;
#pragma unroll
                        for (int nt = 0; nt < 8; ++nt) {
                            const int c0 = warpN + nt * 8 + 2 * qd;
                            *(uint32_t*)(g_vh + ((size_t)hh * LTOK + grow) * HDIM + c0) =
                                packh2(acc[mt][nt][h2 * 2 + 0], acc[mt][nt][h2 * 2 + 1]);
                        }
                    }
            } else {
#pragma unroll
                for (int mt = 0; mt < 4; ++mt)
#pragma unroll
                    for (int h2 = 0; h2 < 2; ++h2) {
                        ssp[mt][h2] += __shfl_xor_sync(0xffffffffu, ssp[mt][h2], 1);
                        ssp[mt][h2] += __shfl_xor_sync(0xffffffffu, ssp[mt][h2], 2);
                    }
                float* red = (float*)smh;
                __syncthreads();
                if (qd == 0) {
#pragma unroll
                    for (int mt = 0; mt < 4; ++mt)
#pragma unroll
                        for (int h2 = 0; h2 < 2; ++h2)
                            red[(warpM + mt * 16 + gp + h2 * 8) * 2 + (warpN >> 6)] =
                                ssp[mt][h2];
                }
                __syncthreads();
                const float* sc = (btype == 0) ? q_scale : k_scale;
                __half* dst = (btype == 0) ? g_qh : g_kh;
                const float fin = (btype == 0) ? SM_SCALE * LOG2E : 1.0f;
#pragma unroll
                for (int mt = 0; mt < 4; ++mt)
#pragma unroll
                    for (int h2 = 0; h2 < 2; ++h2) {
                        const int lrow = warpM + mt * 16 + gp + h2 * 8;
                        const float ss = red[lrow * 2 + 0] + red[lrow * 2 + 1];
                        const float rstd = rsqrtf(ss * (1.0f / HDIM) + EPSV);
                        const int grow = bm + lrow;
#pragma unroll
                        for (int nt = 0; nt < 8; ++nt) {
                            const int c0 = warpN + nt * 8 + 2 * qd;
                            float v0 = acc[mt][nt][h2 * 2 + 0] * rstd * sc[c0];
                            float v1 = acc[mt][nt][h2 * 2 + 1] * rstd * sc[c0 + 1];
                            float4 f = *(const float4*)(pe +
                                ((size_t)grow * (HDIM / 2) + (c0 >> 1)) * 4);
                            float o0 = f.x * v0 + f.y * v1;
                            float o1 = f.z * v0 + f.w * v1;
                            *(uint32_t*)(dst + ((size_t)hh * LTOK + grow) * HDIM + c0) =
                                packh2(o0 * fin, o1 * fin);
                        }
                    }
            }
        }
    } else if (EPI == 2) {
#pragma unroll
        for (int nt = 0; nt < 8; ++nt) {
            const int col = bn + warpN + nt * 8 + 2 * qd;
            const float b0 = bias[col], b1v = bias[col + 1];
#pragma unroll
            for (int mt = 0; mt < 4; ++mt) {
#pragma unroll
                for (int h2 = 0; h2 < 2; ++h2) {
                    const int row = bm + warpM + mt * 16 + gp + h2 * 8;
                    const size_t off = (size_t)row * Nt + col;
                    *(float2*)(C + off) = make_float2(acc[mt][nt][h2 * 2 + 0] + b0,
                                                      acc[mt][nt][h2 * 2 + 1] + b1v);
                }
            }
        }
    } else {
#pragma unroll
        for (int nt = 0; nt < 8; ++nt) {
            const int col = bn + warpN + nt * 8 + 2 * qd;
            const float g0 = gate[col], g1 = gate[col + 1];
#pragma unroll
            for (int mt = 0; mt < 4; ++mt) {
#pragma unroll
                for (int h2 = 0; h2 < 2; ++h2) {
                    const int row = bm + warpM + mt * 16 + gp + h2 * 8;
                    const size_t off = (size_t)row * Nt + col;
                    float2 xr = *(const float2*)(xres + off);
                    float2 pp = *(const float2*)(partial + off);
                    float v0 = xr.x + g0 * (pp.x + acc[mt][nt][h2 * 2 + 0]);
                    float v1 = xr.y + g1 * (pp.y + acc[mt][nt][h2 * 2 + 1]);
                    *(float2*)(C + off) = make_float2(v0, v1);
                }
            }
        }
    }
}

// ---------------------------------------------------------------------------
// Flash attention fp16 mma: Q tile 64, 128 threads, 2 CTAs/SM (R13 validated)
// ---------------------------------------------------------------------------
#define KSH 136
#define KVBUF (64 * KSH * 2)
#define FL_SMEM (4 * KVBUF)
#define FTHREADS 128

__device__ __forceinline__ void load_kv(uint32_t kd, uint32_t vd,
                                        const __half* __restrict__ Kg,
                                        const __half* __restrict__ Vg,
                                        int kt, int tid) {
#pragma unroll
    for (int it = 0; it < 8; ++it) {
        int id = it * FTHREADS + tid;
        int row = id >> 4, c = id & 15;
        uint32_t off = (uint32_t)(row * KSH * 2 + c * 16);
        const size_t goff = (size_t)(kt + row) * HDIM + c * 8;
        cp_async16(kd + off, Kg + goff);
        cp_async16(vd + off, Vg + goff);
    }
}

__global__ void __launch_bounds__(FTHREADS, 2) flash_h() {
    extern __shared__ __half smh[];
    const uint32_t kbase0 = smem_u32(smh);
    const uint32_t vbase0 = kbase0 + 2 * KVBUF;

    const int h = blockIdx.y;
    const int qb = blockIdx.x * 64;
    const int tid = threadIdx.x;
    const int w = tid >> 5, lane = tid & 31;
    const int gp = lane >> 2, qd = lane & 3;

    const __half* Kg = g_kh + (size_t)h * LTOK * HDIM;
    const __half* Vg = g_vh + (size_t)h * LTOK * HDIM;

    uint32_t qf[8][4];
    {
        const __half* q0 = g_qh + ((size_t)h * LTOK + qb + w * 16 + gp) * HDIM;
        const __half* q1 = q0 + 8 * HDIM;
#pragma unroll
        for (int ks = 0; ks < 8; ++ks) {
            int c = ks * 16 + 2 * qd;
            qf[ks][0] = *(const uint32_t*)(q0 + c);
            qf[ks][1] = *(const uint32_t*)(q1 + c);
            qf[ks][2] = *(const uint32_t*)(q0 + c + 8);
            qf[ks][3] = *(const uint32_t*)(q1 + c + 8);
        }
    }

    float ofr[16][4] = {};
    float m0 = -1e30f, m1 = -1e30f, l0 = 0.f, l1 = 0.f;

    load_kv(kbase0, vbase0, Kg, Vg, 0, tid);
    asm volatile("cp.async.commit_group;" ::: "memory");

    const int nT = LTOK / 64;
    for (int t = 0; t < nT; ++t) {
        const int buf = t & 1;
        asm volatile("cp.async.wait_group 0;" ::: "memory");
        __syncthreads();
        if (t + 1 < nT)
            load_kv(kbase0 + (buf ^ 1) * KVBUF, vbase0 + (buf ^ 1) * KVBUF,
                    Kg, Vg, (t + 1) * 64, tid);
        asm volatile("cp.async.commit_group;" ::: "memory");

        const uint32_t kb = kbase0 + buf * KVBUF;
        const uint32_t vb = vbase0 + buf * KVBUF;

        float sfr[8][4] = {};
#pragma unroll
        for (int nt = 0; nt < 8; ++nt) {
            uint32_t bb[8][2];
#pragma unroll
            for (int j = 0; j < 4; ++j) {
                uint32_t ad = kb + (uint32_t)(((nt * 8 + (lane & 7)) * KSH +
                                               j * 32 + (lane >> 3) * 8) * 2);
                uint32_t r[4];
                ldsm4(r, ad);
                bb[2 * j][0] = r[0]; bb[2 * j][1] = r[1];
                bb[2 * j + 1][0] = r[2]; bb[2 * j + 1][1] = r[3];
            }
#pragma unroll
            for (int ks = 0; ks < 8; ++ks)
                mma_f16(sfr[nt], qf[ks], bb[ks][0], bb[ks][1]);
        }

        float mx0 = -1e30f, mx1 = -1e30f;
#pragma unroll
        for (int nt = 0; nt < 8; ++nt) {
            mx0 = fmaxf(mx0, fmaxf(sfr[nt][0], sfr[nt][1]));
            mx1 = fmaxf(mx1, fmaxf(sfr[nt][2], sfr[nt][3]));
        }
        mx0 = fmaxf(mx0, __shfl_xor_sync(0xffffffffu, mx0, 1));
        mx0 = fmaxf(mx0, __shfl_xor_sync(0xffffffffu, mx0, 2));
        mx1 = fmaxf(mx1, __shfl_xor_sync(0xffffffffu, mx1, 1));
        mx1 = fmaxf(mx1, __shfl_xor_sync(0xffffffffu, mx1, 2));
        float mn0 = fmaxf(m0, mx0), mn1 = fmaxf(m1, mx1);
        float a0 = exp2f(m0 - mn0), a1 = exp2f(m1 - mn1);
        m0 = mn0; m1 = mn1;

        float rs0 = 0.f, rs1 = 0.f;
#pragma unroll
        for (int nt = 0; nt < 8; ++nt) {
            sfr[nt][0] = exp2f(sfr[nt][0] - mn0);
            sfr[nt][1] = exp2f(sfr[nt][1] - mn0);
            sfr[nt][2] = exp2f(sfr[nt][2] - mn1);
            sfr[nt][3] = exp2f(sfr[nt][3] - mn1);
            rs0 += sfr[nt][0] + sfr[nt][1];
            rs1 += sfr[nt][2] + sfr[nt][3];
        }
        rs0 += __shfl_xor_sync(0xffffffffu, rs0, 1);
        rs0 += __shfl_xor_sync(0xffffffffu, rs0, 2);
        rs1 += __shfl_xor_sync(0xffffffffu, rs1, 1);
        rs1 += __shfl_xor_sync(0xffffffffu, rs1, 2);
        l0 = l0 * a0 + rs0;
        l1 = l1 * a1 + rs1;

        uint32_t pf[4][4];
#pragma unroll
        for (int ks2 = 0; ks2 < 4; ++ks2) {
            pf[ks2][0] = packh2(sfr[2 * ks2][0], sfr[2 * ks2][1]);
            pf[ks2][1] = packh2(sfr[2 * ks2][2], sfr[2 * ks2][3]);
            pf[ks2][2] = packh2(sfr[2 * ks2 + 1][0], sfr[2 * ks2 + 1][1]);
            pf[ks2][3] = packh2(sfr[2 * ks2 + 1][2], sfr[2 * ks2 + 1][3]);
        }

#pragma unroll
        for (int nt = 0; nt < 16; ++nt) {
            ofr[nt][0] *= a0; ofr[nt][1] *= a0;
            ofr[nt][2] *= a1; ofr[nt][3] *= a1;
        }

#pragma unroll
        for (int nt2 = 0; nt2 < 8; ++nt2) {
#pragma unroll
            for (int ks2 = 0; ks2 < 4; ++ks2) {
                uint32_t ad = vb + (uint32_t)(((ks2 * 16 + (lane & 15)) * KSH +
                                               (2 * nt2 + (lane >> 4)) * 8) * 2);
                uint32_t r[4];
                ldsm4t(r, ad);
                mma_f16(ofr[2 * nt2], pf[ks2], r[0], r[1]);
                mma_f16(ofr[2 * nt2 + 1], pf[ks2], r[2], r[3]);
            }
        }
    }

    float inv0 = 1.0f / l0, inv1 = 1.0f / l1;
    __half* o0 = g_cath + (size_t)(qb + w * 16 + gp) * K2 + h * HDIM;
    __half* o1 = o0 + (size_t)8 * K2;
#pragma unroll
    for (int nt = 0; nt < 16; ++nt) {
        int c = nt * 8 + 2 * qd;
        *(uint32_t*)(o0 + c) = packh2(ofr[nt][0] * inv0, ofr[nt][1] * inv0);
        *(uint32_t*)(o1 + c) = packh2(ofr[nt][2] * inv1, ofr[nt][3] * inv1);
    }
}

// ---------------------------------------------------------------------------
// launch (R14/R16 schedule -- best validated): side stream carries weight cvt
// and GEMM2a (mlp K-half of GEMM2), overlapping flash. GEMM2b joins, finishes.
// ---------------------------------------------------------------------------
extern "C" void kernel_launch(void* const* d_in, const int* in_sizes, int n_in,
                              void* d_out, int out_size) {
    const float* x   = (const float*)d_in[0];
    const float* vec = (const float*)d_in[1];
    const float* pe  = (const float*)d_in[2];
    const float* w1  = (const float*)d_in[3];
    const float* b1  = (const float*)d_in[4];
    const float* w2  = (const float*)d_in[5];
    const float* b2  = (const float*)d_in[6];
    const float* mw  = (const float*)d_in[7];
    const float* mb  = (const float*)d_in[8];
    const float* qsc = (const float*)d_in[9];
    const float* ksc = (const float*)d_in[10];
    float* out = (float*)d_out;

    __half *p_xmodh, *p_cath, *p_w1h, *p_w2h;
    float *p_m, *p_out1;
    cudaGetSymbolAddress((void**)&p_xmodh, g_xmodh);
    cudaGetSymbolAddress((void**)&p_cath, g_cath);
    cudaGetSymbolAddress((void**)&p_m, g_m);
    cudaGetSymbolAddress((void**)&p_w1h, g_w1h);
    cudaGetSymbolAddress((void**)&p_w2h, g_w2h);
    cudaGetSymbolAddress((void**)&p_out1, g_out1);

    cudaFuncSetAttribute(flash_h, cudaFuncAttributeMaxDynamicSharedMemorySize, FL_SMEM);
    cudaFuncSetAttribute(mm_gemm<0>, cudaFuncAttributeMaxDynamicSharedMemorySize, GEMM_SMEM);
    cudaFuncSetAttribute(mm_gemm<2>, cudaFuncAttributeMaxDynamicSharedMemorySize, GEMM_SMEM);
    cudaFuncSetAttribute(mm_gemm<3>, cudaFuncAttributeMaxDynamicSharedMemorySize, GEMM_SMEM);

    cudaStream_t s2;
    cudaStreamCreateWithFlags(&s2, cudaStreamNonBlocking);
    cudaEvent_t e0, e1, e3, e4;
    cudaEventCreateWithFlags(&e0, cudaEventDisableTiming);
    cudaEventCreateWithFlags(&e1, cudaEventDisableTiming);
    cudaEventCreateWithFlags(&e3, cudaEventDisableTiming);
    cudaEventCreateWithFlags(&e4, cudaEventDisableTiming);

    cudaEventRecord(e0, 0);
    cudaStreamWaitEvent(s2, e0, 0);

    // side stream: weight conversions
    cvt_h_k<<<(W1_N4 + 255) / 256, 256, 0, s2>>>(w1, p_w1h, W1_N4);
    cudaEventRecord(e1, s2);
    cvt_h_k<<<(W2_N4 + 255) / 256, 256, 0, s2>>>(w2, p_w2h, W2_N4);

    // main stream: preamble (silu folded into mod_gemv)
    mod_gemv<<<(3 * DMODEL) / 8, 256>>>(vec, mw, mb);
    ln_mod<<<LTOK, 256>>>(x);

    cudaStreamWaitEvent(0, e1, 0);

    // GEMM1 fused (main, full width)
    mm_gemm<0><<<dim3(LTOK / BM, N1 / BN), GTHREADS, GEMM_SMEM>>>(
        p_xmodh, p_w1h, nullptr, N1, DMODEL, DMODEL, DMODEL, 0,
        b1, nullptr, nullptr, nullptr, pe, qsc, ksc);
    cudaEventRecord(e3, 0);

    // side stream: GEMM2a (mlp K-half) overlaps flash
    cudaStreamWaitEvent(s2, e3, 0);
    mm_gemm<2><<<dim3(LTOK / BM, DMODEL / BN), GTHREADS, GEMM_SMEM, s2>>>(
        p_cath + DMODEL, p_w2h + DMODEL, p_out1, DMODEL, MLPD, K2, K2, 0,
        b2, nullptr, nullptr, nullptr, nullptr, nullptr, nullptr);
    cudaEventRecord(e4, s2);

    // main stream: flash
    flash_h<<<dim3(LTOK / 64, NHEAD), FTHREADS, FL_SMEM>>>();

    // join: GEMM2b = attn K-half + partial + residual/gate
    cudaStreamWaitEvent(0, e4, 0);
    mm_gemm<3><<<dim3(LTOK / BM, DMODEL / BN), GTHREADS, GEMM_SMEM>>>(
        p_cath, p_w2h, out, DMODEL, DMODEL, K2, K2, 0,
        nullptr, x, p_m + 2 * DMODEL, p_out1, nullptr, nullptr, nullptr);
}